// round 1
// baseline (speedup 1.0000x reference)
#include <cuda_runtime.h>
#include <math.h>

#define NB 16
#define RR 256
#define AA 256
#define HEADS 8
#define HC 32
#define P576 576
#define D484 484
#define DPAD 488

// ---------------- scratch (static device arrays; no allocs) ----------------
__device__ float g_xin[NB * RR * P576];          // 9.4 MB
__device__ float g_q[NB * AA * P576];            // 9.4 MB
__device__ float g_k[NB * AA * D484];            // 7.9 MB
__device__ float g_v[NB * AA * D484];            // 7.9 MB
__device__ float g_a[NB * AA * P576];            // 9.4 MB
__device__ float g_gates[NB * 4 * RR * P576];    // 37.7 MB
__device__ float g_h[NB * RR * P576];            // 9.4 MB

// ---------------- 1x1 conv == per-n GEMM: y[n,co,p] = sum_ci w[co,ci]*x[n,ci,p] + b ----
// grid: (P/64, Cout/64, N), block 256. 64x64 tile, K-chunk 8, 4x4 per thread.
__global__ __launch_bounds__(256) void conv1x1_kernel(
    const float* __restrict__ x, const float* __restrict__ w,
    const float* __restrict__ b, float* __restrict__ y,
    int Cin, int Cout, int accum)
{
    const int n = blockIdx.z, cot = blockIdx.y, pt = blockIdx.x;
    const int tid = threadIdx.x;
    const int tx = tid & 15, ty = tid >> 4;

    __shared__ float As[8][64];
    __shared__ float Bs[8][64];

    const float* xb = x + (size_t)n * Cin * P576 + pt * 64;
    const float* wb = w + (size_t)cot * 64 * Cin;

    float acc[4][4];
#pragma unroll
    for (int i = 0; i < 4; i++)
#pragma unroll
        for (int j = 0; j < 4; j++) acc[i][j] = 0.f;

    for (int k0 = 0; k0 < Cin; k0 += 8) {
        __syncthreads();
#pragma unroll
        for (int l = 0; l < 2; ++l) {
            int e = tid + l * 256;
            int m = e >> 3, kk = e & 7;
            As[kk][m] = wb[(size_t)m * Cin + k0 + kk];
            int kk2 = e >> 6, nn = e & 63;
            Bs[kk2][nn] = xb[(size_t)(k0 + kk2) * P576 + nn];
        }
        __syncthreads();
#pragma unroll
        for (int kk = 0; kk < 8; ++kk) {
            float4 av = *(const float4*)&As[kk][ty * 4];
            float4 bv = *(const float4*)&Bs[kk][tx * 4];
            acc[0][0] += av.x * bv.x; acc[0][1] += av.x * bv.y; acc[0][2] += av.x * bv.z; acc[0][3] += av.x * bv.w;
            acc[1][0] += av.y * bv.x; acc[1][1] += av.y * bv.y; acc[1][2] += av.y * bv.z; acc[1][3] += av.y * bv.w;
            acc[2][0] += av.z * bv.x; acc[2][1] += av.z * bv.y; acc[2][2] += av.z * bv.z; acc[2][3] += av.z * bv.w;
            acc[3][0] += av.w * bv.x; acc[3][1] += av.w * bv.y; acc[3][2] += av.w * bv.z; acc[3][3] += av.w * bv.w;
        }
    }

#pragma unroll
    for (int i = 0; i < 4; ++i) {
        int co = cot * 64 + ty * 4 + i;
        float bias = b ? b[co] : 0.f;
#pragma unroll
        for (int j = 0; j < 4; ++j) {
            size_t idx = ((size_t)n * Cout + co) * P576 + pt * 64 + tx * 4 + j;
            float val = acc[i][j] + bias;
            if (accum) val += y[idx];
            y[idx] = val;
        }
    }
}

// ---------------- dual 3x3 conv: y = conv3(x1,w1) + conv3(x2,w2) (+bias) -----
// x1,x2: [N,256,24,24]. w: [Cout,256,3,3]. pad=1 -> SAME (OH=24); pad=0 -> VALID (OH=22).
// grid: (Cout/16, N), block 576. Thread = 4 out-ch x 4 horizontal pixels.
__global__ __launch_bounds__(576, 2) void dualconv3_kernel(
    const float* __restrict__ x1, const float* __restrict__ x2,
    const float* __restrict__ w1, const float* __restrict__ w2,
    const float* __restrict__ bias, float* __restrict__ y,
    int Cout, int OH, int pad)
{
    const int n = blockIdx.y;
    const int cog = blockIdx.x;
    const int tid = threadIdx.x;
    const int cosub = tid / 144;          // 0..3  -> out channels cosub*4..+3
    const int pos = tid % 144;            // 24 rows x 6 col-groups
    const int row = pos / 6;
    const int x0 = (pos % 6) * 4;

    __shared__ float s_in[26 * 27];
    __shared__ float s_w[16 * 9];

    float acc[4][4];
#pragma unroll
    for (int i = 0; i < 4; i++)
#pragma unroll
        for (int j = 0; j < 4; j++) acc[i][j] = 0.f;

    // zero full tile (keeps halo / unused rows at 0)
    for (int e = tid; e < 26 * 27; e += 576) s_in[e] = 0.f;

    const int iy = tid / 24;
    const int ix = tid % 24;
    const int sidx = (iy + pad) * 27 + (ix + pad);

    for (int c = 0; c < 512; ++c) {
        __syncthreads();
        const float* src = (c < 256) ? (x1 + (size_t)(n * 256 + c) * P576)
                                     : (x2 + (size_t)(n * 256 + (c - 256)) * P576);
        s_in[sidx] = src[tid];
        if (tid < 144) {
            const float* wsrc = (c < 256) ? w1 : w2;
            int co = tid / 9, kk = tid % 9;
            int cc = (c < 256) ? c : (c - 256);
            s_w[tid] = wsrc[((size_t)(cog * 16 + co) * 256 + cc) * 9 + kk];
        }
        __syncthreads();

#pragma unroll
        for (int ky = 0; ky < 3; ++ky) {
            float r[6];
#pragma unroll
            for (int j = 0; j < 6; ++j) r[j] = s_in[(row + ky) * 27 + x0 + j];
#pragma unroll
            for (int kx = 0; kx < 3; ++kx) {
#pragma unroll
                for (int i = 0; i < 4; ++i) {
                    float wv = s_w[(cosub * 4 + i) * 9 + ky * 3 + kx];
                    acc[i][0] += wv * r[kx + 0];
                    acc[i][1] += wv * r[kx + 1];
                    acc[i][2] += wv * r[kx + 2];
                    acc[i][3] += wv * r[kx + 3];
                }
            }
        }
    }

    if (row < OH) {
#pragma unroll
        for (int i = 0; i < 4; ++i) {
            int co = cog * 16 + cosub * 4 + i;
            float bv = bias ? bias[co] : 0.f;
#pragma unroll
            for (int j = 0; j < 4; ++j) {
                int xx = x0 + j;
                if (xx < OH) {
                    y[(((size_t)n * Cout + co) * OH + row) * OH + xx] = acc[i][j] + bv;
                }
            }
        }
    }
}

// ---------------- fused attention per (n, head): softmax(q^T k) -> v @ p ----
// grid: (4 q-chunks of 144 rows, HEADS, N), block 256.
// dynamic smem: k[32][488] + v[32][488] (125 KB).
__global__ void attn_kernel(const float* __restrict__ q, const float* __restrict__ k,
                            const float* __restrict__ v, float* __restrict__ a)
{
    extern __shared__ float dyn[];
    float* sk = dyn;
    float* sv = dyn + 32 * DPAD;
    __shared__ __align__(16) float sq[32 * 4];
    __shared__ __align__(16) float sp[D484 * 4];
    __shared__ float red[8 * 4];
    __shared__ float bmax[4];
    __shared__ float bsum[4];

    const int n = blockIdx.z, g = blockIdx.y, qc = blockIdx.x;
    const int tid = threadIdx.x;
    const int lane = tid & 31, wid = tid >> 5;

    const size_t kvbase = (size_t)(n * HEADS + g) * HC * D484;
    for (int e = tid; e < HC * D484; e += 256) {
        int c = e / D484, d = e % D484;
        sk[c * DPAD + d] = k[kvbase + e];
        sv[c * DPAD + d] = v[kvbase + e];
    }

    const size_t qbase = (size_t)(n * HEADS + g) * HC * P576;
    const size_t abase = ((size_t)n * AA + g * HC) * P576;

    const int d1 = tid, d2 = tid + 256;
    const bool has2 = (d2 < D484);

    for (int r0 = qc * 144; r0 < qc * 144 + 144; r0 += 4) {
        __syncthreads();  // also covers sk/sv load on first iter, protects sq/sp reuse
        if (tid < 128) {
            int c = tid >> 2, r = tid & 3;
            sq[c * 4 + r] = q[qbase + (size_t)c * P576 + r0 + r];
        }
        __syncthreads();

        // scores: each thread owns d1 (and d2 if valid), all 4 q-rows
        float s1[4] = {0, 0, 0, 0}, s2[4] = {0, 0, 0, 0};
#pragma unroll 8
        for (int c = 0; c < 32; ++c) {
            float4 qv = *(const float4*)&sq[c * 4];
            float k1 = sk[c * DPAD + d1];
            float k2 = has2 ? sk[c * DPAD + d2] : 0.f;
            s1[0] += k1 * qv.x; s1[1] += k1 * qv.y; s1[2] += k1 * qv.z; s1[3] += k1 * qv.w;
            s2[0] += k2 * qv.x; s2[1] += k2 * qv.y; s2[2] += k2 * qv.z; s2[3] += k2 * qv.w;
        }

        // row-wise max reduce
        float lm[4];
#pragma unroll
        for (int r = 0; r < 4; r++) lm[r] = has2 ? fmaxf(s1[r], s2[r]) : s1[r];
#pragma unroll
        for (int off = 16; off; off >>= 1) {
#pragma unroll
            for (int r = 0; r < 4; r++)
                lm[r] = fmaxf(lm[r], __shfl_xor_sync(0xffffffffu, lm[r], off));
        }
        if (lane == 0) {
#pragma unroll
            for (int r = 0; r < 4; r++) red[wid * 4 + r] = lm[r];
        }
        __syncthreads();
        if (tid < 4) {
            float m = red[tid];
            for (int w = 1; w < 8; w++) m = fmaxf(m, red[w * 4 + tid]);
            bmax[tid] = m;
        }
        __syncthreads();

        // exp + store p (transposed: sp[d][r]) + sum reduce
        float ls[4] = {0, 0, 0, 0};
        float e1[4], e2[4];
#pragma unroll
        for (int r = 0; r < 4; r++) {
            e1[r] = __expf(s1[r] - bmax[r]);
            ls[r] += e1[r];
            e2[r] = 0.f;
            if (has2) { e2[r] = __expf(s2[r] - bmax[r]); ls[r] += e2[r]; }
        }
        *(float4*)&sp[d1 * 4] = make_float4(e1[0], e1[1], e1[2], e1[3]);
        if (has2) *(float4*)&sp[d2 * 4] = make_float4(e2[0], e2[1], e2[2], e2[3]);
#pragma unroll
        for (int off = 16; off; off >>= 1) {
#pragma unroll
            for (int r = 0; r < 4; r++)
                ls[r] += __shfl_xor_sync(0xffffffffu, ls[r], off);
        }
        if (lane == 0) {
#pragma unroll
            for (int r = 0; r < 4; r++) red[wid * 4 + r] = ls[r];
        }
        __syncthreads();
        if (tid < 4) {
            float m = 0.f;
            for (int w = 0; w < 8; w++) m += red[w * 4 + tid];
            bsum[tid] = 1.f / m;
        }
        __syncthreads();

        // AV: thread (c = tid>>3, j = tid&7) strides d by 8
        int c = tid >> 3, j = tid & 7;
        float acc[4] = {0, 0, 0, 0};
        for (int d = j; d < D484; d += 8) {
            float vv = sv[c * DPAD + d];
            float4 pv = *(const float4*)&sp[d * 4];
            acc[0] += vv * pv.x; acc[1] += vv * pv.y; acc[2] += vv * pv.z; acc[3] += vv * pv.w;
        }
#pragma unroll
        for (int off = 4; off; off >>= 1) {
#pragma unroll
            for (int r = 0; r < 4; r++)
                acc[r] += __shfl_down_sync(0xffffffffu, acc[r], off, 8);
        }
        if (j == 0) {
#pragma unroll
            for (int r = 0; r < 4; r++)
                a[abase + (size_t)c * P576 + r0 + r] = acc[r] * bsum[r];
        }
    }
}

// ---------------- LSTM elementwise ----------------
__global__ void lstm_kernel(const float* __restrict__ gates, const float* __restrict__ c0,
                            float* __restrict__ h)
{
    int idx = blockIdx.x * blockDim.x + threadIdx.x;
    if (idx >= NB * RR * P576) return;
    int n = idx / (RR * P576);
    int rp = idx % (RR * P576);
    size_t gb = (size_t)n * 4 * RR * P576 + rp;
    float gi = gates[gb];
    float gf = gates[gb + (size_t)RR * P576];
    float gg = gates[gb + (size_t)2 * RR * P576];
    float go = gates[gb + (size_t)3 * RR * P576];
    float si = 1.f / (1.f + __expf(-gi));
    float sf = 1.f / (1.f + __expf(-gf));
    float so = 1.f / (1.f + __expf(-go));
    float c = sf * c0[idx] + si * tanhf(gg);
    h[idx] = so * tanhf(c);
}

// ---------------- launch ----------------
extern "C" void kernel_launch(void* const* d_in, const int* in_sizes, int n_in,
                              void* d_out, int out_size)
{
    const float* x     = (const float*)d_in[0];
    const float* h0    = (const float*)d_in[1];
    const float* c0    = (const float*)d_in[2];
    const float* w_in  = (const float*)d_in[3];
    const float* b_in  = (const float*)d_in[4];
    const float* wq_x  = (const float*)d_in[5];
    const float* wq_h  = (const float*)d_in[6];
    const float* wk_x  = (const float*)d_in[7];
    const float* wk_h  = (const float*)d_in[8];
    const float* wv_x  = (const float*)d_in[9];
    const float* wv_h  = (const float*)d_in[10];
    const float* bv    = (const float*)d_in[11];
    const float* wg_a  = (const float*)d_in[12];
    const float* bg    = (const float*)d_in[13];
    const float* wg_x  = (const float*)d_in[14];
    const float* wg_h  = (const float*)d_in[15];
    const float* w_out = (const float*)d_in[16];
    const float* b_out = (const float*)d_in[17];
    float* out = (float*)d_out;

    float *p_xin, *p_q, *p_k, *p_v, *p_a, *p_gates, *p_h;
    cudaGetSymbolAddress((void**)&p_xin, g_xin);
    cudaGetSymbolAddress((void**)&p_q, g_q);
    cudaGetSymbolAddress((void**)&p_k, g_k);
    cudaGetSymbolAddress((void**)&p_v, g_v);
    cudaGetSymbolAddress((void**)&p_a, g_a);
    cudaGetSymbolAddress((void**)&p_gates, g_gates);
    cudaGetSymbolAddress((void**)&p_h, g_h);

    // 1. xin = 1x1(x) + b_in
    conv1x1_kernel<<<dim3(9, 4, NB), 256>>>(x, w_in, b_in, p_xin, 128, 256, 0);

    // 2-5. dual 3x3 convs
    dualconv3_kernel<<<dim3(16, NB), 576>>>(p_xin, h0, wq_x, wq_h, nullptr, p_q, 256, 24, 1);
    dualconv3_kernel<<<dim3(16, NB), 576>>>(p_xin, h0, wk_x, wk_h, nullptr, p_k, 256, 22, 0);
    dualconv3_kernel<<<dim3(16, NB), 576>>>(p_xin, h0, wv_x, wv_h, bv, p_v, 256, 22, 0);
    dualconv3_kernel<<<dim3(64, NB), 576>>>(p_xin, h0, wg_x, wg_h, nullptr, p_gates, 1024, 24, 1);

    // 6. attention
    const int ATTN_SMEM = 2 * 32 * DPAD * (int)sizeof(float);  // ~125 KB
    cudaFuncSetAttribute(attn_kernel, cudaFuncAttributeMaxDynamicSharedMemorySize, ATTN_SMEM);
    attn_kernel<<<dim3(4, HEADS, NB), 256, ATTN_SMEM>>>(p_q, p_k, p_v, p_a);

    // 7. gates += wg_a @ a + bg
    conv1x1_kernel<<<dim3(9, 16, NB), 256>>>(p_a, wg_a, bg, p_gates, 256, 1024, 1);

    // 8. LSTM elementwise -> h
    lstm_kernel<<<(NB * RR * P576 + 255) / 256, 256>>>(p_gates, c0, p_h);

    // 9. out = 1x1(h) + b_out
    conv1x1_kernel<<<dim3(9, 4, NB), 256>>>(p_h, w_out, b_out, out, 256, 256, 0);
}

// round 3
// speedup vs baseline: 2.5962x; 2.5962x over previous
#include <cuda_runtime.h>
#include <cuda_bf16.h>
#include <math.h>
#include <cstdint>

#define NB 16
#define RR 256
#define AA 256
#define HEADS 8
#define HC 32
#define P576 576
#define D484 484
#define DPAD 488
#define KTOT 4608
#define SROWS (NB * P576)      /* 9216 */
#define VROWS (NB * D484)      /* 7744 */
#define VROWS_PAD 7808
#define M1 1280
#define M2 512

// ---------------- scratch (static device arrays; no allocs) ----------------
__device__ float g_xin[NB * RR * P576];
__device__ float g_q[NB * AA * P576];
__device__ float g_k[NB * AA * D484];
__device__ float g_v[NB * AA * D484];
__device__ float g_a[NB * AA * P576];
__device__ float g_gates[NB * 4 * RR * P576];
__device__ float g_h[NB * RR * P576];

// bf16 split GEMM operands
__device__ __nv_bfloat16 g_A1h[M1 * KTOT];
__device__ __nv_bfloat16 g_A1l[M1 * KTOT];
__device__ __nv_bfloat16 g_A2h[M2 * KTOT];
__device__ __nv_bfloat16 g_A2l[M2 * KTOT];
__device__ __nv_bfloat16 g_Bsh[(size_t)SROWS * KTOT];
__device__ __nv_bfloat16 g_Bsl[(size_t)SROWS * KTOT];
__device__ __nv_bfloat16 g_Bvh[(size_t)VROWS_PAD * KTOT];
__device__ __nv_bfloat16 g_Bvl[(size_t)VROWS_PAD * KTOT];

// ---------------- helpers ----------------
__device__ __forceinline__ uint32_t smem_u32(const void* p) {
    uint32_t a;
    asm("{ .reg .u64 t; cvta.to.shared.u64 t, %1; cvt.u32.u64 %0, t; }" : "=r"(a) : "l"(p));
    return a;
}
__device__ __forceinline__ void cpa16(uint32_t dst, const void* src) {
    asm volatile("cp.async.cg.shared.global [%0], [%1], 16;" :: "r"(dst), "l"(src));
}
#define CPA_COMMIT() asm volatile("cp.async.commit_group;" ::: "memory")

#define LDMX4(r, addr) \
    asm volatile("ldmatrix.sync.aligned.m8n8.x4.shared.b16 {%0,%1,%2,%3}, [%4];" \
                 : "=r"((r)[0]), "=r"((r)[1]), "=r"((r)[2]), "=r"((r)[3]) : "r"(addr))

__device__ __forceinline__ void mma16816(float* c, const uint32_t* a, const uint32_t* b) {
    asm volatile(
        "mma.sync.aligned.m16n8k16.row.col.f32.bf16.bf16.f32 "
        "{%0,%1,%2,%3}, {%4,%5,%6,%7}, {%8,%9}, {%0,%1,%2,%3};"
        : "+f"(c[0]), "+f"(c[1]), "+f"(c[2]), "+f"(c[3])
        : "r"(a[0]), "r"(a[1]), "r"(a[2]), "r"(a[3]), "r"(b[0]), "r"(b[1]));
}

__device__ __forceinline__ void split_bf16(float x, __nv_bfloat16& h, __nv_bfloat16& l) {
    h = __float2bfloat16(x);
    l = __float2bfloat16(x - __bfloat162float(h));
}

// ---------------- 1x1 conv GEMM (fp32) ----------------
__global__ __launch_bounds__(256) void conv1x1_kernel(
    const float* __restrict__ x, const float* __restrict__ w,
    const float* __restrict__ b, float* __restrict__ y,
    int Cin, int Cout, int accum)
{
    const int n = blockIdx.z, cot = blockIdx.y, pt = blockIdx.x;
    const int tid = threadIdx.x;
    const int tx = tid & 15, ty = tid >> 4;

    __shared__ float As[8][64];
    __shared__ float Bs[8][64];

    const float* xb = x + (size_t)n * Cin * P576 + pt * 64;
    const float* wb = w + (size_t)cot * 64 * Cin;

    float acc[4][4];
#pragma unroll
    for (int i = 0; i < 4; i++)
#pragma unroll
        for (int j = 0; j < 4; j++) acc[i][j] = 0.f;

    for (int k0 = 0; k0 < Cin; k0 += 8) {
        __syncthreads();
#pragma unroll
        for (int l = 0; l < 2; ++l) {
            int e = tid + l * 256;
            int m = e >> 3, kk = e & 7;
            As[kk][m] = wb[(size_t)m * Cin + k0 + kk];
            int kk2 = e >> 6, nn = e & 63;
            Bs[kk2][nn] = xb[(size_t)(k0 + kk2) * P576 + nn];
        }
        __syncthreads();
#pragma unroll
        for (int kk = 0; kk < 8; ++kk) {
            float4 av = *(const float4*)&As[kk][ty * 4];
            float4 bv = *(const float4*)&Bs[kk][tx * 4];
            acc[0][0] += av.x * bv.x; acc[0][1] += av.x * bv.y; acc[0][2] += av.x * bv.z; acc[0][3] += av.x * bv.w;
            acc[1][0] += av.y * bv.x; acc[1][1] += av.y * bv.y; acc[1][2] += av.y * bv.z; acc[1][3] += av.y * bv.w;
            acc[2][0] += av.z * bv.x; acc[2][1] += av.z * bv.y; acc[2][2] += av.z * bv.z; acc[2][3] += av.z * bv.w;
            acc[3][0] += av.w * bv.x; acc[3][1] += av.w * bv.y; acc[3][2] += av.w * bv.z; acc[3][3] += av.w * bv.w;
        }
    }

#pragma unroll
    for (int i = 0; i < 4; ++i) {
        int co = cot * 64 + ty * 4 + i;
        float bias = b ? b[co] : 0.f;
#pragma unroll
        for (int j = 0; j < 4; ++j) {
            size_t idx = ((size_t)n * Cout + co) * P576 + pt * 64 + tx * 4 + j;
            float val = acc[i][j] + bias;
            if (accum) val += y[idx];
            y[idx] = val;
        }
    }
}

// ---------------- weight prep: A[m][kk*512+c] hi/lo bf16 -------------------
__global__ __launch_bounds__(64) void prep_w_kernel(
    const float* __restrict__ wq_x, const float* __restrict__ wq_h,
    const float* __restrict__ wk_x, const float* __restrict__ wk_h,
    const float* __restrict__ wv_x, const float* __restrict__ wv_h,
    const float* __restrict__ wg_x, const float* __restrict__ wg_h)
{
    int m = blockIdx.x;
    int c0 = threadIdx.x * 8;
    const float *wx, *wh;
    __nv_bfloat16 *Ah, *Al;
    int mloc, arow;
    if (m < 256)        { wx = wq_x; wh = wq_h; mloc = m;        arow = m;              Ah = g_A1h; Al = g_A1l; }
    else if (m < 1280)  { wx = wg_x; wh = wg_h; mloc = m - 256;  arow = m;              Ah = g_A1h; Al = g_A1l; }
    else if (m < 1536)  { wx = wk_x; wh = wk_h; mloc = m - 1280; arow = m - 1280;       Ah = g_A2h; Al = g_A2l; }
    else                { wx = wv_x; wh = wv_h; mloc = m - 1536; arow = m - 1536 + 256; Ah = g_A2h; Al = g_A2l; }

    const float* w = (c0 < 256) ? wx + ((size_t)mloc * 256 + c0) * 9
                                : wh + ((size_t)mloc * 256 + (c0 - 256)) * 9;
#pragma unroll
    for (int kk = 0; kk < 9; ++kk) {
        union { __nv_bfloat16 b[8]; uint4 u; } ph, pl;
#pragma unroll
        for (int j = 0; j < 8; ++j) {
            float x = w[j * 9 + kk];
            split_bf16(x, ph.b[j], pl.b[j]);
        }
        size_t off = (size_t)arow * KTOT + kk * 512 + c0;
        *(uint4*)&Ah[off] = ph.u;
        *(uint4*)&Al[off] = pl.u;
    }
}

// ---------------- im2col -> bf16 hi/lo ----------------
__global__ __launch_bounds__(256) void im2col_kernel(
    const float* __restrict__ xin, const float* __restrict__ h0)
{
    extern __shared__ float s[];  // [32][577]
    const int ct = blockIdx.x, n = blockIdx.y, mode = blockIdx.z;
    const float* src = (ct < 8) ? xin + ((size_t)n * 256 + ct * 32) * P576
                                : h0 + ((size_t)n * 256 + (ct - 8) * 32) * P576;
    for (int e = threadIdx.x; e < 32 * 144; e += 256) {
        int ch = e / 144, v = e % 144;
        float4 f = ((const float4*)src)[ch * 144 + v];
        int base = ch * 577 + v * 4;
        s[base] = f.x; s[base + 1] = f.y; s[base + 2] = f.z; s[base + 3] = f.w;
    }
    __syncthreads();

    const int cbase = ct * 32;
    if (mode == 0) {
#pragma unroll
        for (int kk = 0; kk < 9; ++kk) {
            int ky = kk / 3 - 1, kx = kk % 3 - 1;
            for (int e = threadIdx.x; e < 576 * 4; e += 256) {
                int p = e >> 2, oct = e & 3;
                int y = p / 24, x = p % 24;
                int iy = y + ky, ix = x + kx;
                bool ok = (iy >= 0) && (iy < 24) && (ix >= 0) && (ix < 24);
                int sp = iy * 24 + ix;
                union { __nv_bfloat16 b[8]; uint4 u; } ph, pl;
#pragma unroll
                for (int j = 0; j < 8; ++j) {
                    float v = ok ? s[(oct * 8 + j) * 577 + sp] : 0.f;
                    split_bf16(v, ph.b[j], pl.b[j]);
                }
                size_t off = (size_t)(n * 576 + p) * KTOT + kk * 512 + cbase + oct * 8;
                *(uint4*)&g_Bsh[off] = ph.u;
                *(uint4*)&g_Bsl[off] = pl.u;
            }
        }
    } else {
#pragma unroll
        for (int kk = 0; kk < 9; ++kk) {
            int ky = kk / 3, kx = kk % 3;
            for (int e = threadIdx.x; e < 484 * 4; e += 256) {
                int p = e >> 2, oct = e & 3;
                int y = p / 22, x = p % 22;
                int sp = (y + ky) * 24 + (x + kx);
                union { __nv_bfloat16 b[8]; uint4 u; } ph, pl;
#pragma unroll
                for (int j = 0; j < 8; ++j) {
                    float v = s[(oct * 8 + j) * 577 + sp];
                    split_bf16(v, ph.b[j], pl.b[j]);
                }
                size_t off = (size_t)(n * 484 + p) * KTOT + kk * 512 + cbase + oct * 8;
                *(uint4*)&g_Bvh[off] = ph.u;
                *(uint4*)&g_Bvl[off] = pl.u;
            }
        }
    }
}

__global__ void padB_kernel() {
    size_t row = 7744 + blockIdx.x;  // 64 blocks
    uint4 z = make_uint4(0, 0, 0, 0);
    for (int e = threadIdx.x; e < KTOT / 8; e += blockDim.x) {
        ((uint4*)&g_Bvh[row * KTOT])[e] = z;
        ((uint4*)&g_Bvl[row * KTOT])[e] = z;
    }
}

// ---------------- bf16-split mma.sync GEMM ----------------------------------
// C[m, col] = Ah·Bh + Al·Bh + Ah·Bl (fp32 accum). Tile 128x128, K-stage 32.
// 8 warps: warp (wm = wid&1, wn = wid>>1) computes 64x32. 3-stage cp.async.
#define KCH 32
#define NSTAGE 3
#define ROWB 80                      /* 32 bf16 + 8 pad => conflict-free ldmatrix */
#define TILE_BYTES (128 * ROWB)      /* 10240 */
#define STAGE_BYTES (4 * TILE_BYTES) /* Ah, Al, Bh, Bl */
#define GEMM_SMEM (NSTAGE * STAGE_BYTES)
#define KSTAGES (KTOT / KCH)         /* 144 */

__global__ __launch_bounds__(256, 1) void gemm_kernel(
    const __nv_bfloat16* __restrict__ Ahp, const __nv_bfloat16* __restrict__ Alp,
    const __nv_bfloat16* __restrict__ Bhp, const __nv_bfloat16* __restrict__ Blp,
    const float* __restrict__ bias, int mode, int ncols)
{
    extern __shared__ char sm[];
    const uint32_t sbase = smem_u32(sm);
    const int tid = threadIdx.x, lane = tid & 31, wid = tid >> 5;
    const int wm = wid & 1, wn = wid >> 1;
    const int mt = blockIdx.x, nt = blockIdx.y;
    const size_t arow0 = (size_t)mt * 128, brow0 = (size_t)nt * 128;

    float acc[4][4][4];
#pragma unroll
    for (int a = 0; a < 4; a++)
#pragma unroll
        for (int b = 0; b < 4; b++)
#pragma unroll
            for (int c = 0; c < 4; c++) acc[a][b][c] = 0.f;

    // per-lane ldmatrix offsets
    const int a_row = (lane & 7) + ((lane >> 3) & 1) * 8;
    const int a_byte = ((lane >> 4) & 1) * 16;
    const int b_row = (lane & 7) + ((lane >> 4) & 1) * 8;
    const int b_byte = ((lane >> 3) & 1) * 16;

    // cp.async: thread's chunk for step t: tile = t>>1, row = (t&1)*64 + tid/4, ch = tid&3
    const int ld_row_lo = tid >> 2;
    const int ld_ch = tid & 3;

    auto load_stage = [&](int s) {
        const uint32_t base = sbase + (s % NSTAGE) * STAGE_BYTES;
        const int k0 = s * KCH;
        const __nv_bfloat16* srcs[4] = {Ahp, Alp, Bhp, Blp};
        const size_t row0s[4] = {arow0, arow0, brow0, brow0};
#pragma unroll
        for (int t = 0; t < 8; ++t) {
            const int tile = t >> 1;
            const int row = (t & 1) * 64 + ld_row_lo;
            const uint32_t dst = base + tile * TILE_BYTES + row * ROWB + ld_ch * 16;
            cpa16(dst, srcs[tile] + (row0s[tile] + row) * (size_t)KTOT + k0 + ld_ch * 8);
        }
    };

    auto compute_stage = [&](int s) {
        const uint32_t base = sbase + (s % NSTAGE) * STAGE_BYTES;
#pragma unroll
        for (int j = 0; j < 2; ++j) {
            uint32_t rah[4][4], ral[4][4];
#pragma unroll
            for (int mf = 0; mf < 4; ++mf) {
                uint32_t addr = base + (wm * 64 + mf * 16 + a_row) * ROWB + j * 32 + a_byte;
                LDMX4(rah[mf], addr);
                LDMX4(ral[mf], addr + TILE_BYTES);
            }
            uint32_t rbh[2][4], rbl[2][4];
#pragma unroll
            for (int nf2 = 0; nf2 < 2; ++nf2) {
                uint32_t addr = base + 2 * TILE_BYTES +
                                (wn * 32 + nf2 * 16 + b_row) * ROWB + j * 32 + b_byte;
                LDMX4(rbh[nf2], addr);
                LDMX4(rbl[nf2], addr + TILE_BYTES);
            }
#pragma unroll
            for (int mf = 0; mf < 4; ++mf)
#pragma unroll
                for (int nf = 0; nf < 4; ++nf) {
                    const uint32_t* bh = &rbh[nf >> 1][(nf & 1) * 2];
                    const uint32_t* bl = &rbl[nf >> 1][(nf & 1) * 2];
                    mma16816(acc[mf][nf], rah[mf], bh);
                    mma16816(acc[mf][nf], ral[mf], bh);
                    mma16816(acc[mf][nf], rah[mf], bl);
                }
        }
    };

    load_stage(0); CPA_COMMIT();
    load_stage(1); CPA_COMMIT();

    for (int i = 0; i < KSTAGES; ++i) {
        if (i + 2 < KSTAGES) load_stage(i + 2);
        CPA_COMMIT();
        asm volatile("cp.async.wait_group 2;" ::: "memory");
        __syncthreads();
        compute_stage(i);
        __syncthreads();
    }

    // epilogue: direct scatter to NCHW outputs
    const int mrow0 = mt * 128 + wm * 64;
    const int col0 = nt * 128 + wn * 32;
    const int stride = (mode == 0) ? 576 : 484;
#pragma unroll
    for (int mf = 0; mf < 4; ++mf) {
#pragma unroll
        for (int nf = 0; nf < 4; ++nf) {
            const int m0 = mrow0 + mf * 16 + (lane >> 2);
            const int c0 = col0 + nf * 8 + (lane & 3) * 2;
#pragma unroll
            for (int e = 0; e < 4; ++e) {
                const int m = m0 + (e >> 1) * 8;
                const int col = c0 + (e & 1);
                const float v = acc[mf][nf][e];
                if (col < ncols) {
                    const int n = col / stride, sp = col - n * stride;
                    if (mode == 0) {
                        if (m < 256) g_q[((size_t)n * 256 + m) * 576 + sp] = v;
                        else g_gates[((size_t)n * 1024 + (m - 256)) * 576 + sp] = v;
                    } else {
                        if (m < 256) g_k[((size_t)n * 256 + m) * 484 + sp] = v;
                        else g_v[((size_t)n * 256 + (m - 256)) * 484 + sp] = v + bias[m - 256];
                    }
                }
            }
        }
    }
}

// ---------------- fused attention per (n, head) ----------------
__global__ void attn_kernel(const float* __restrict__ q, const float* __restrict__ k,
                            const float* __restrict__ v, float* __restrict__ a)
{
    extern __shared__ float dyn[];
    float* sk = dyn;
    float* sv = dyn + 32 * DPAD;
    __shared__ __align__(16) float sq[32 * 4];
    __shared__ __align__(16) float sp[D484 * 4];
    __shared__ float red[8 * 4];
    __shared__ float bmax[4];
    __shared__ float bsum[4];

    const int n = blockIdx.z, g = blockIdx.y, qc = blockIdx.x;
    const int tid = threadIdx.x;
    const int lane = tid & 31, wid = tid >> 5;

    const size_t kvbase = (size_t)(n * HEADS + g) * HC * D484;
    for (int e = tid; e < HC * D484; e += 256) {
        int c = e / D484, d = e % D484;
        sk[c * DPAD + d] = k[kvbase + e];
        sv[c * DPAD + d] = v[kvbase + e];
    }

    const size_t qbase = (size_t)(n * HEADS + g) * HC * P576;
    const size_t abase = ((size_t)n * AA + g * HC) * P576;

    const int d1 = tid, d2 = tid + 256;
    const bool has2 = (d2 < D484);

    for (int r0 = qc * 144; r0 < qc * 144 + 144; r0 += 4) {
        __syncthreads();
        if (tid < 128) {
            int c = tid >> 2, r = tid & 3;
            sq[c * 4 + r] = q[qbase + (size_t)c * P576 + r0 + r];
        }
        __syncthreads();

        float s1[4] = {0, 0, 0, 0}, s2[4] = {0, 0, 0, 0};
#pragma unroll 8
        for (int c = 0; c < 32; ++c) {
            float4 qv = *(const float4*)&sq[c * 4];
            float k1 = sk[c * DPAD + d1];
            float k2 = has2 ? sk[c * DPAD + d2] : 0.f;
            s1[0] += k1 * qv.x; s1[1] += k1 * qv.y; s1[2] += k1 * qv.z; s1[3] += k1 * qv.w;
            s2[0] += k2 * qv.x; s2[1] += k2 * qv.y; s2[2] += k2 * qv.z; s2[3] += k2 * qv.w;
        }

        float lm[4];
#pragma unroll
        for (int r = 0; r < 4; r++) lm[r] = has2 ? fmaxf(s1[r], s2[r]) : s1[r];
#pragma unroll
        for (int off = 16; off; off >>= 1)
#pragma unroll
            for (int r = 0; r < 4; r++)
                lm[r] = fmaxf(lm[r], __shfl_xor_sync(0xffffffffu, lm[r], off));
        if (lane == 0)
#pragma unroll
            for (int r = 0; r < 4; r++) red[wid * 4 + r] = lm[r];
        __syncthreads();
        if (tid < 4) {
            float m = red[tid];
            for (int w = 1; w < 8; w++) m = fmaxf(m, red[w * 4 + tid]);
            bmax[tid] = m;
        }
        __syncthreads();

        float ls[4] = {0, 0, 0, 0};
        float e1[4], e2[4];
#pragma unroll
        for (int r = 0; r < 4; r++) {
            e1[r] = __expf(s1[r] - bmax[r]);
            ls[r] += e1[r];
            e2[r] = 0.f;
            if (has2) { e2[r] = __expf(s2[r] - bmax[r]); ls[r] += e2[r]; }
        }
        *(float4*)&sp[d1 * 4] = make_float4(e1[0], e1[1], e1[2], e1[3]);
        if (has2) *(float4*)&sp[d2 * 4] = make_float4(e2[0], e2[1], e2[2], e2[3]);
#pragma unroll
        for (int off = 16; off; off >>= 1)
#pragma unroll
            for (int r = 0; r < 4; r++)
                ls[r] += __shfl_xor_sync(0xffffffffu, ls[r], off);
        if (lane == 0)
#pragma unroll
            for (int r = 0; r < 4; r++) red[wid * 4 + r] = ls[r];
        __syncthreads();
        if (tid < 4) {
            float m = 0.f;
            for (int w = 0; w < 8; w++) m += red[w * 4 + tid];
            bsum[tid] = 1.f / m;
        }
        __syncthreads();

        int c = tid >> 3, j = tid & 7;
        float acc[4] = {0, 0, 0, 0};
        for (int d = j; d < D484; d += 8) {
            float vv = sv[c * DPAD + d];
            float4 pv = *(const float4*)&sp[d * 4];
            acc[0] += vv * pv.x; acc[1] += vv * pv.y; acc[2] += vv * pv.z; acc[3] += vv * pv.w;
        }
#pragma unroll
        for (int off = 4; off; off >>= 1)
#pragma unroll
            for (int r = 0; r < 4; r++)
                acc[r] += __shfl_down_sync(0xffffffffu, acc[r], off, 8);
        if (j == 0)
#pragma unroll
            for (int r = 0; r < 4; r++)
                a[abase + (size_t)c * P576 + r0 + r] = acc[r] * bsum[r];
    }
}

// ---------------- LSTM elementwise ----------------
__global__ void lstm_kernel(const float* __restrict__ gates, const float* __restrict__ c0,
                            float* __restrict__ h)
{
    int idx = blockIdx.x * blockDim.x + threadIdx.x;
    if (idx >= NB * RR * P576) return;
    int n = idx / (RR * P576);
    int rp = idx % (RR * P576);
    size_t gb = (size_t)n * 4 * RR * P576 + rp;
    float gi = gates[gb];
    float gf = gates[gb + (size_t)RR * P576];
    float gg = gates[gb + (size_t)2 * RR * P576];
    float go = gates[gb + (size_t)3 * RR * P576];
    float si = 1.f / (1.f + __expf(-gi));
    float sf = 1.f / (1.f + __expf(-gf));
    float so = 1.f / (1.f + __expf(-go));
    float c = sf * c0[idx] + si * tanhf(gg);
    h[idx] = so * tanhf(c);
}

// ---------------- launch ----------------
extern "C" void kernel_launch(void* const* d_in, const int* in_sizes, int n_in,
                              void* d_out, int out_size)
{
    const float* x     = (const float*)d_in[0];
    const float* h0    = (const float*)d_in[1];
    const float* c0    = (const float*)d_in[2];
    const float* w_in  = (const float*)d_in[3];
    const float* b_in  = (const float*)d_in[4];
    const float* wq_x  = (const float*)d_in[5];
    const float* wq_h  = (const float*)d_in[6];
    const float* wk_x  = (const float*)d_in[7];
    const float* wk_h  = (const float*)d_in[8];
    const float* wv_x  = (const float*)d_in[9];
    const float* wv_h  = (const float*)d_in[10];
    const float* bv    = (const float*)d_in[11];
    const float* wg_a  = (const float*)d_in[12];
    const float* bg    = (const float*)d_in[13];
    const float* wg_x  = (const float*)d_in[14];
    const float* wg_h  = (const float*)d_in[15];
    const float* w_out = (const float*)d_in[16];
    const float* b_out = (const float*)d_in[17];
    float* out = (float*)d_out;

    float *p_xin, *p_q, *p_k, *p_v, *p_a, *p_gates, *p_h;
    cudaGetSymbolAddress((void**)&p_xin, g_xin);
    cudaGetSymbolAddress((void**)&p_q, g_q);
    cudaGetSymbolAddress((void**)&p_k, g_k);
    cudaGetSymbolAddress((void**)&p_v, g_v);
    cudaGetSymbolAddress((void**)&p_a, g_a);
    cudaGetSymbolAddress((void**)&p_gates, g_gates);
    cudaGetSymbolAddress((void**)&p_h, g_h);
    __nv_bfloat16 *pA1h, *pA1l, *pA2h, *pA2l, *pBsh, *pBsl, *pBvh, *pBvl;
    cudaGetSymbolAddress((void**)&pA1h, g_A1h);
    cudaGetSymbolAddress((void**)&pA1l, g_A1l);
    cudaGetSymbolAddress((void**)&pA2h, g_A2h);
    cudaGetSymbolAddress((void**)&pA2l, g_A2l);
    cudaGetSymbolAddress((void**)&pBsh, g_Bsh);
    cudaGetSymbolAddress((void**)&pBsl, g_Bsl);
    cudaGetSymbolAddress((void**)&pBvh, g_Bvh);
    cudaGetSymbolAddress((void**)&pBvl, g_Bvl);

    // 1. xin = 1x1(x) + b_in
    conv1x1_kernel<<<dim3(9, 4, NB), 256>>>(x, w_in, b_in, p_xin, 128, 256, 0);

    // 2. weight prep (independent of xin) + valid-pad rows
    prep_w_kernel<<<1792, 64>>>(wq_x, wq_h, wk_x, wk_h, wv_x, wv_h, wg_x, wg_h);
    padB_kernel<<<64, 256>>>();

    // 3. im2col (after xin)
    const int IM2_SMEM = 32 * 577 * (int)sizeof(float);
    cudaFuncSetAttribute(im2col_kernel, cudaFuncAttributeMaxDynamicSharedMemorySize, IM2_SMEM);
    im2col_kernel<<<dim3(16, NB, 2), 256, IM2_SMEM>>>(p_xin, h0);

    // 4. tensor-core GEMMs (q+gates, then k+v)
    cudaFuncSetAttribute(gemm_kernel, cudaFuncAttributeMaxDynamicSharedMemorySize, GEMM_SMEM);
    gemm_kernel<<<dim3(M1 / 128, SROWS / 128), 256, GEMM_SMEM>>>(
        pA1h, pA1l, pBsh, pBsl, bv, 0, SROWS);
    gemm_kernel<<<dim3(M2 / 128, VROWS_PAD / 128), 256, GEMM_SMEM>>>(
        pA2h, pA2l, pBvh, pBvl, bv, 1, VROWS);

    // 5. attention
    const int ATTN_SMEM = 2 * 32 * DPAD * (int)sizeof(float);
    cudaFuncSetAttribute(attn_kernel, cudaFuncAttributeMaxDynamicSharedMemorySize, ATTN_SMEM);
    attn_kernel<<<dim3(4, HEADS, NB), 256, ATTN_SMEM>>>(p_q, p_k, p_v, p_a);

    // 6. gates += wg_a @ a + bg
    conv1x1_kernel<<<dim3(9, 16, NB), 256>>>(p_a, wg_a, bg, p_gates, 256, 1024, 1);

    // 7. LSTM elementwise -> h
    lstm_kernel<<<(NB * RR * P576 + 255) / 256, 256>>>(p_gates, c0, p_h);

    // 8. out = 1x1(h) + b_out
    conv1x1_kernel<<<dim3(9, 4, NB), 256>>>(p_h, w_out, b_out, out, 256, 256, 0);
}